// round 10
// baseline (speedup 1.0000x reference)
#include <cuda_runtime.h>
#include <stdint.h>
#include <math.h>

// Problem constants
#define BB  4
#define TT  1024
#define DD  768
#define NCH 7
#define BT  (BB*TT)   // 4096 rows

// ---------------------------------------------------------------------------
// Scratch (device globals; no allocation allowed in kernel_launch)
// ---------------------------------------------------------------------------
__device__ float g_h   [(size_t)BT*DD];
__device__ float g_in  [(size_t)BT*DD];
__device__ float g_seq [(size_t)BT*DD];
__device__ float g_par [(size_t)BT*DD];
// parallel branch (chambers indexed 0..6; chamber 0 slot of q/k/o unused)
__device__ float g_q   [(size_t)NCH*BT*DD];
__device__ float g_k   [(size_t)NCH*BT*DD];
__device__ float g_o   [(size_t)NCH*BT*DD];
__device__ float g_d   [(size_t)NCH*BT*DD];
__device__ float g_S   [(size_t)NCH*BB*TT*TT];
// sequential-branch private buffers (avoid races with concurrent s1 work)
__device__ float g_q2  [(size_t)BT*DD];
__device__ float g_k2  [(size_t)BT*DD];
__device__ float g_o2  [(size_t)BT*DD];
__device__ float g_S2  [(size_t)BB*TT*TT];
// TF32-rounded weight copies
__device__ float g_wq  [(size_t)NCH*DD*DD];
__device__ float g_wk  [(size_t)NCH*DD*DD];
__device__ float g_mw  [(size_t)DD*NCH*DD];

// ---------------------------------------------------------------------------
// TF32 helpers
// ---------------------------------------------------------------------------
__device__ __forceinline__ uint32_t f2tf(float f) {
    uint32_t r;
    asm("cvt.rna.tf32.f32 %0, %1;" : "=r"(r) : "f"(f));
    return r;
}
__device__ __forceinline__ float tf32r(float f) { return __uint_as_float(f2tf(f)); }

__device__ __forceinline__ void mma_tf32(float c[4],
    uint32_t a0, uint32_t a1, uint32_t a2, uint32_t a3,
    uint32_t b0, uint32_t b1)
{
    asm volatile(
        "mma.sync.aligned.m16n8k8.row.col.f32.tf32.tf32.f32 "
        "{%0,%1,%2,%3}, {%4,%5,%6,%7}, {%8,%9}, {%0,%1,%2,%3};"
        : "+f"(c[0]), "+f"(c[1]), "+f"(c[2]), "+f"(c[3])
        : "r"(a0), "r"(a1), "r"(a2), "r"(a3), "r"(b0), "r"(b1));
}
#define CPA16(saddr, gptr) \
    asm volatile("cp.async.cg.shared.global [%0], [%1], 16;" :: "r"(saddr), "l"(gptr))
#define CPA_COMMIT() asm volatile("cp.async.commit_group;")
#define CPA_WAIT0()  asm volatile("cp.async.wait_group 0;")

// ---------------------------------------------------------------------------
// TF32 MMA GEMM: C = round_tf32( alpha * A @ op(B) (+ C if ACC) )
// ALL operands must already be TF32-rounded fp32 (producers round at write).
// No cvt in the inner loop — raw bit reinterpretation.
//   A: M x K row-major (lda). kchunk>0: K-concat of chunks (merge GEMM).
//   B: TRANSB ? N x K row-major : K x N row-major. bmod>0 -> B uses z%bmod.
//   CSKIP: skip C tiles fully above diagonal. CKLIM: cap K at tile diagonal.
// Tiles 128x128x16, 8 warps, 64x32 warp tile, cp.async double buffer.
// ---------------------------------------------------------------------------
#define ASTRIDE 20
#define BSTRIDE 136
#define AS_SZ  (128*ASTRIDE)
#define STG_SZ (2*AS_SZ)

template<bool TRANSB, bool ACC, bool CSKIP, bool CKLIM>
__global__ void __launch_bounds__(256, 2)
mma_gemm(const float* __restrict__ A, int lda, long long sA,
         const float* __restrict__ Bp, int ldb, long long sB, int bmod,
         float* __restrict__ C, int ldc, long long sC,
         int M, int N, int K, float alpha,
         int kchunk, long long schunk)
{
    const int m0 = blockIdx.y * 128;
    const int n0 = blockIdx.x * 128;
    if (CSKIP && n0 > m0 + 127) return;

    const int z = blockIdx.z;
    A  += (long long)z * sA;
    Bp += (long long)(bmod ? (z % bmod) : z) * sB;
    C  += (long long)z * sC;

    int kend = K;
    if (CKLIM) { int ke = m0 + 128; kend = (ke < K) ? ke : K; }
    const int niter = kend >> 4;

    __shared__ float sm[2][STG_SZ];

    const int tid  = threadIdx.x;
    const int wid  = tid >> 5;
    const int lane = tid & 31;
    const int gid  = lane >> 2;
    const int tig  = lane & 3;
    const int wm   = (wid & 1) * 64;
    const int wn   = (wid >> 1) * 32;

    float acc[4][4][4];
    #pragma unroll
    for (int i = 0; i < 4; i++)
        #pragma unroll
        for (int j = 0; j < 4; j++)
            #pragma unroll
            for (int r = 0; r < 4; r++) acc[i][j][r] = 0.f;

    auto loadA = [&](int stg, int k0) {
        const float* Ab;
        if (kchunk) { int c = k0 / kchunk; Ab = A + (long long)c * schunk + (k0 - c * kchunk); }
        else        Ab = A + k0;
        float* as = sm[stg];
        #pragma unroll
        for (int i = 0; i < 2; i++) {
            int idx = tid + i * 256;
            int r = idx >> 2, c4 = (idx & 3) << 2;
            uint32_t sa = (uint32_t)__cvta_generic_to_shared(&as[r * ASTRIDE + c4]);
            CPA16(sa, Ab + (long long)(m0 + r) * lda + c4);
        }
    };
    auto loadB = [&](int stg, int k0) {
        float* bs = sm[stg] + AS_SZ;
        if (TRANSB) {
            #pragma unroll
            for (int i = 0; i < 2; i++) {
                int idx = tid + i * 256;
                int r = idx >> 2, c4 = (idx & 3) << 2;
                uint32_t sa = (uint32_t)__cvta_generic_to_shared(&bs[r * ASTRIDE + c4]);
                CPA16(sa, Bp + (long long)(n0 + r) * ldb + k0 + c4);
            }
        } else {
            #pragma unroll
            for (int i = 0; i < 2; i++) {
                int idx = tid + i * 256;
                int r = idx >> 5, c4 = (idx & 31) << 2;
                uint32_t sa = (uint32_t)__cvta_generic_to_shared(&bs[r * BSTRIDE + c4]);
                CPA16(sa, Bp + (long long)(k0 + r) * ldb + n0 + c4);
            }
        }
    };

    loadA(0, 0); loadB(0, 0);
    CPA_COMMIT();

    for (int it = 0; it < niter; ++it) {
        CPA_WAIT0();
        __syncthreads();
        if (it + 1 < niter) {
            loadA((it + 1) & 1, (it + 1) << 4);
            loadB((it + 1) & 1, (it + 1) << 4);
            CPA_COMMIT();
        }
        const float* as = sm[it & 1];
        const float* bs = as + AS_SZ;

        #pragma unroll
        for (int kk = 0; kk < 16; kk += 8) {
            uint32_t a[4][4];
            #pragma unroll
            for (int mi = 0; mi < 4; mi++) {
                int mb = wm + mi * 16 + gid;
                a[mi][0] = __float_as_uint(as[ mb      * ASTRIDE + kk + tig    ]);
                a[mi][1] = __float_as_uint(as[(mb + 8) * ASTRIDE + kk + tig    ]);
                a[mi][2] = __float_as_uint(as[ mb      * ASTRIDE + kk + tig + 4]);
                a[mi][3] = __float_as_uint(as[(mb + 8) * ASTRIDE + kk + tig + 4]);
            }
            uint32_t b[4][2];
            #pragma unroll
            for (int ni = 0; ni < 4; ni++) {
                int nb = wn + ni * 8 + gid;
                if (TRANSB) {
                    b[ni][0] = __float_as_uint(bs[nb * ASTRIDE + kk + tig    ]);
                    b[ni][1] = __float_as_uint(bs[nb * ASTRIDE + kk + tig + 4]);
                } else {
                    b[ni][0] = __float_as_uint(bs[(kk + tig    ) * BSTRIDE + nb]);
                    b[ni][1] = __float_as_uint(bs[(kk + tig + 4) * BSTRIDE + nb]);
                }
            }
            #pragma unroll
            for (int mi = 0; mi < 4; mi++)
                #pragma unroll
                for (int ni = 0; ni < 4; ni++)
                    mma_tf32(acc[mi][ni], a[mi][0], a[mi][1], a[mi][2], a[mi][3],
                             b[ni][0], b[ni][1]);
        }
    }

    // epilogue — output is TF32-rounded so downstream GEMMs can skip cvt
    #pragma unroll
    for (int mi = 0; mi < 4; mi++) {
        #pragma unroll
        for (int ni = 0; ni < 4; ni++) {
            const int rr = m0 + wm + mi * 16 + gid;
            const int cc = n0 + wn + ni * 8 + tig * 2;
            #pragma unroll
            for (int hh = 0; hh < 2; hh++) {
                long long idx = (long long)(rr + hh * 8) * ldc + cc;
                float2 v;
                v.x = alpha * acc[mi][ni][hh * 2 + 0];
                v.y = alpha * acc[mi][ni][hh * 2 + 1];
                if (ACC) {
                    float2 c = *reinterpret_cast<const float2*>(&C[idx]);
                    v.x += c.x; v.y += c.y;
                }
                v.x = tf32r(v.x);
                v.y = tf32r(v.y);
                *reinterpret_cast<float2*>(&C[idx]) = v;
            }
        }
    }
}

// ---------------------------------------------------------------------------
// Elementwise TF32 rounding copy (for weights), float4 vectorized
// ---------------------------------------------------------------------------
__global__ void round_tf32_kernel(const float* __restrict__ in,
                                  float* __restrict__ out, int n4)
{
    int i = blockIdx.x * 256 + threadIdx.x;
    if (i < n4) {
        float4 v = reinterpret_cast<const float4*>(in)[i];
        v.x = tf32r(v.x); v.y = tf32r(v.y); v.z = tf32r(v.z); v.w = tf32r(v.w);
        reinterpret_cast<float4*>(out)[i] = v;
    }
}

// ---------------------------------------------------------------------------
// Causal softmax in place (rows of [nz][T][T]); output TF32-rounded,
// zero-fill to 128 tile boundary.
// ---------------------------------------------------------------------------
__global__ void __launch_bounds__(256)
softmax_causal_kernel(float* __restrict__ S)
{
    __shared__ float red[256];
    const int r = blockIdx.x;
    const int zb = r / TT, t = r % TT;
    float* row = S + (long long)zb * TT * TT + (long long)t * TT;
    const int valid = t + 1;
    const int tid = threadIdx.x;

    float mx = -1e30f;
    for (int s = tid; s < valid; s += 256) mx = fmaxf(mx, row[s]);
    red[tid] = mx; __syncthreads();
    for (int o = 128; o > 0; o >>= 1) {
        if (tid < o) red[tid] = fmaxf(red[tid], red[tid + o]);
        __syncthreads();
    }
    mx = red[0]; __syncthreads();

    float sum = 0.f;
    for (int s = tid; s < valid; s += 256) {
        float e = expf(row[s] - mx);
        row[s] = e;
        sum += e;
    }
    red[tid] = sum; __syncthreads();
    for (int o = 128; o > 0; o >>= 1) {
        if (tid < o) red[tid] += red[tid + o];
        __syncthreads();
    }
    const float inv = 1.f / red[0];

    for (int s = tid; s < valid; s += 256) row[s] = tf32r(row[s] * inv);
    const int zend = ((valid + 127) / 128) * 128;
    for (int s = valid + tid; s < zend; s += 256) row[s] = 0.f;
}

// ---------------------------------------------------------------------------
// Chamber 0 combine: v = softplus(sp0)*sigmoid(h.gw0+gb0)*(O-h)
// delta0 = round(v); seq = v   (curriculum masks are exactly 1.0)
// ---------------------------------------------------------------------------
__global__ void __launch_bounds__(256)
combine_c0_kernel(const float* __restrict__ In, const float* __restrict__ O,
                  const float* __restrict__ gw, const float* __restrict__ gb,
                  const float* __restrict__ sp,
                  float* __restrict__ delta, float* __restrict__ seq)
{
    __shared__ float red[256];
    const int r = blockIdx.x;
    const long long base = (long long)r * DD;
    const int tid = threadIdx.x;

    float dot = 0.f;
    for (int d = tid; d < DD; d += 256) dot += In[base + d] * gw[d];
    red[tid] = dot; __syncthreads();
    for (int o = 128; o > 0; o >>= 1) {
        if (tid < o) red[tid] += red[tid + o];
        __syncthreads();
    }
    const float gate = 1.f / (1.f + expf(-(red[0] + gb[0])));
    const float s = sp[0];
    float coef = (s > 20.f) ? s : log1pf(expf(s));
    coef *= gate;

    for (int d = tid; d < DD; d += 256) {
        const float v = coef * (O[base + d] - In[base + d]);
        delta[base + d] = tf32r(v);
        seq[base + d] = v;
    }
}

// ---------------------------------------------------------------------------
// Parallel combine for chambers 1..6 (blockIdx.y = ch-1): delta_ch = round(v)
// ---------------------------------------------------------------------------
__global__ void __launch_bounds__(256)
combine_par6_kernel(const float* __restrict__ hIn, const float* __restrict__ o6,
                    const float* __restrict__ gw, const float* __restrict__ gb,
                    const float* __restrict__ sp, float* __restrict__ delta6)
{
    __shared__ float red[256];
    const int i  = blockIdx.y;          // 0..5 -> chamber i+1
    const int r  = blockIdx.x;
    const long long base  = (long long)r * DD;
    const long long cbase = (long long)i * BT * DD + base;
    const int tid = threadIdx.x;
    const float* gwi = gw + (size_t)(i + 1) * DD;

    float dot = 0.f;
    for (int d = tid; d < DD; d += 256) dot += hIn[base + d] * gwi[d];
    red[tid] = dot; __syncthreads();
    for (int o = 128; o > 0; o >>= 1) {
        if (tid < o) red[tid] += red[tid + o];
        __syncthreads();
    }
    const float gate = 1.f / (1.f + expf(-(red[0] + gb[i + 1])));
    const float s = sp[i + 1];
    float coef = (s > 20.f) ? s : log1pf(expf(s));
    coef *= gate;

    for (int d = tid; d < DD; d += 256)
        delta6[cbase + d] = tf32r(coef * (o6[cbase + d] - hIn[base + d]));
}

// ---------------------------------------------------------------------------
// Sequential combine: seq += softplus(sp)*sigmoid(In.gw+gb)*(O-In)
// ---------------------------------------------------------------------------
__global__ void __launch_bounds__(256)
combine_seq_kernel(const float* __restrict__ In, const float* __restrict__ O,
                   const float* __restrict__ gw, const float* __restrict__ gb,
                   const float* __restrict__ sp, float* __restrict__ seq)
{
    __shared__ float red[256];
    const int r = blockIdx.x;
    const long long base = (long long)r * DD;
    const int tid = threadIdx.x;

    float dot = 0.f;
    for (int d = tid; d < DD; d += 256) dot += In[base + d] * gw[d];
    red[tid] = dot; __syncthreads();
    for (int o = 128; o > 0; o >>= 1) {
        if (tid < o) red[tid] += red[tid + o];
        __syncthreads();
    }
    const float gate = 1.f / (1.f + expf(-(red[0] + gb[0])));
    const float s = sp[0];
    float coef = (s > 20.f) ? s : log1pf(expf(s));
    coef *= gate;

    for (int d = tid; d < DD; d += 256)
        seq[base + d] += coef * (O[base + d] - In[base + d]);
}

// ---------------------------------------------------------------------------
// c = round_tf32(a + b)
// ---------------------------------------------------------------------------
__global__ void add_round_kernel(const float* __restrict__ a,
                                 const float* __restrict__ b,
                                 float* __restrict__ c, int n4)
{
    int i = blockIdx.x * 256 + threadIdx.x;
    if (i < n4) {
        float4 va = reinterpret_cast<const float4*>(a)[i];
        float4 vb = reinterpret_cast<const float4*>(b)[i];
        va.x = tf32r(va.x + vb.x);
        va.y = tf32r(va.y + vb.y);
        va.z = tf32r(va.z + vb.z);
        va.w = tf32r(va.w + vb.w);
        reinterpret_cast<float4*>(c)[i] = va;
    }
}

// ---------------------------------------------------------------------------
// LayerNorm (per row of D=768), output TF32-rounded (feeds GEMMs)
// ---------------------------------------------------------------------------
__global__ void __launch_bounds__(256)
ln_kernel(const float* __restrict__ x, const float* __restrict__ g,
          const float* __restrict__ b, float* __restrict__ out)
{
    __shared__ float r1[256], r2[256];
    const int r = blockIdx.x;
    const long long base = (long long)r * DD;
    const int tid = threadIdx.x;

    float s = 0.f, s2 = 0.f;
    for (int d = tid; d < DD; d += 256) {
        float v = x[base + d];
        s += v; s2 += v * v;
    }
    r1[tid] = s; r2[tid] = s2; __syncthreads();
    for (int o = 128; o > 0; o >>= 1) {
        if (tid < o) { r1[tid] += r1[tid + o]; r2[tid] += r2[tid + o]; }
        __syncthreads();
    }
    const float m   = r1[0] / DD;
    const float var = r2[0] / DD - m * m;
    const float inv = rsqrtf(var + 1e-5f);
    for (int d = tid; d < DD; d += 256)
        out[base + d] = tf32r((x[base + d] - m) * inv * g[d] + b[d]);
}

// ---------------------------------------------------------------------------
__global__ void __launch_bounds__(256)
final_kernel(const float* __restrict__ x, const float* __restrict__ seq,
             const float* __restrict__ par, const float* __restrict__ g,
             const float* __restrict__ b, const float* __restrict__ mode_logit,
             const float* __restrict__ res_gate, float* __restrict__ out)
{
    __shared__ float r1[256], r2[256];
    const int r = blockIdx.x;
    const long long base = (long long)r * DD;
    const int tid = threadIdx.x;

    const float mg = 1.f / (1.f + expf(-mode_logit[0]));
    const float rg = res_gate[0];

    float s = 0.f, s2 = 0.f;
    for (int d = tid; d < DD; d += 256) {
        float e = (1.f - mg) * seq[base + d] + mg * par[base + d];
        s += e; s2 += e * e;
    }
    r1[tid] = s; r2[tid] = s2; __syncthreads();
    for (int o = 128; o > 0; o >>= 1) {
        if (tid < o) { r1[tid] += r1[tid + o]; r2[tid] += r2[tid + o]; }
        __syncthreads();
    }
    const float m   = r1[0] / DD;
    const float var = r2[0] / DD - m * m;
    const float inv = rsqrtf(var + 1e-5f);
    for (int d = tid; d < DD; d += 256) {
        float e  = (1.f - mg) * seq[base + d] + mg * par[base + d];
        float ln = (e - m) * inv * g[d] + b[d];
        out[base + d] = x[base + d] + rg * ln;
    }
}

// ---------------------------------------------------------------------------
extern "C" void kernel_launch(void* const* d_in, const int* in_sizes, int n_in,
                              void* d_out, int out_size)
{
    const float* x             = (const float*)d_in[0];
    const float* Wq            = (const float*)d_in[1];
    const float* Wk            = (const float*)d_in[2];
    const float* gate_w        = (const float*)d_in[3];
    const float* gate_b        = (const float*)d_in[4];
    const float* scale_p       = (const float*)d_in[5];
    const float* merge_W       = (const float*)d_in[6];
    const float* mode_logit    = (const float*)d_in[7];
    const float* residual_gate = (const float*)d_in[8];
    const float* ln_pre_g      = (const float*)d_in[9];
    const float* ln_pre_b      = (const float*)d_in[10];
    const float* ln_post_g     = (const float*)d_in[11];
    const float* ln_post_b     = (const float*)d_in[12];
    float* out = (float*)d_out;

    float *h, *inb, *seq, *par, *q, *k, *o, *dl, *S;
    float *q2, *k2, *o2, *S2, *wq, *wk, *mw;
    cudaGetSymbolAddress((void**)&h,   g_h);
    cudaGetSymbolAddress((void**)&inb, g_in);
    cudaGetSymbolAddress((void**)&seq, g_seq);
    cudaGetSymbolAddress((void**)&par, g_par);
    cudaGetSymbolAddress((void**)&q,   g_q);
    cudaGetSymbolAddress((void**)&k,   g_k);
    cudaGetSymbolAddress((void**)&o,   g_o);
    cudaGetSymbolAddress((void**)&dl,  g_d);
    cudaGetSymbolAddress((void**)&S,   g_S);
    cudaGetSymbolAddress((void**)&q2,  g_q2);
    cudaGetSymbolAddress((void**)&k2,  g_k2);
    cudaGetSymbolAddress((void**)&o2,  g_o2);
    cudaGetSymbolAddress((void**)&S2,  g_S2);
    cudaGetSymbolAddress((void**)&wq,  g_wq);
    cudaGetSymbolAddress((void**)&wk,  g_wk);
    cudaGetSymbolAddress((void**)&mw,  g_mw);

    // Lazily create fork/join resources (host resources, not device memory;
    // created on the first call, reused on the capture call and replays).
    static cudaStream_t s1 = nullptr;
    static cudaEvent_t evF1 = nullptr, evF2 = nullptr, evJ = nullptr;
    if (!s1) {
        cudaStreamCreateWithFlags(&s1, cudaStreamNonBlocking);
        cudaEventCreateWithFlags(&evF1, cudaEventDisableTiming);
        cudaEventCreateWithFlags(&evF2, cudaEventDisableTiming);
        cudaEventCreateWithFlags(&evJ,  cudaEventDisableTiming);
    }

    const float isd = 1.f / sqrtf((float)DD);
    const long long sQK  = (long long)DD * DD;
    const long long sRow = (long long)BT * DD;
    const long long sBT  = (long long)TT * DD;
    const long long sS   = (long long)TT * TT;
    const int wn4 = NCH * DD * DD / 4;

    // -------- weight rounding + pre-LN (stream 0) --------------------------
    round_tf32_kernel<<<(wn4 + 255) / 256, 256>>>(Wq, wq, wn4);
    round_tf32_kernel<<<(wn4 + 255) / 256, 256>>>(Wk, wk, wn4);
    round_tf32_kernel<<<(wn4 + 255) / 256, 256>>>(merge_W, mw, wn4);
    ln_kernel<<<BT, 256>>>(x, ln_pre_g, ln_pre_b, h);

    // -------- fork: s1 runs parallel chambers 1..6 -------------------------
    cudaEventRecord(evF1, 0);
    cudaStreamWaitEvent(s1, evF1, 0);

    mma_gemm<false, false, false, false><<<dim3(6, 32, 6), 256, 0, s1>>>(
        h, DD, 0, wq + sQK, DD, sQK, 0, q + sRow, DD, sRow, BT, DD, DD, 1.f, 0, 0);
    mma_gemm<false, false, false, false><<<dim3(6, 32, 6), 256, 0, s1>>>(
        h, DD, 0, wk + sQK, DD, sQK, 0, k + sRow, DD, sRow, BT, DD, DD, 1.f, 0, 0);
    mma_gemm<true, false, true, false><<<dim3(8, 8, 24), 256, 0, s1>>>(
        q + sRow, DD, sBT, k + sRow, DD, sBT, 0, S, TT, sS, TT, TT, DD, isd, 0, 0);
    softmax_causal_kernel<<<24 * TT, 256, 0, s1>>>(S);
    mma_gemm<false, false, false, true><<<dim3(6, 8, 24), 256, 0, s1>>>(
        S, TT, sS, h, DD, sBT, BB, o + sRow, DD, sBT, TT, DD, TT, 1.f, 0, 0);
    combine_par6_kernel<<<dim3(BT, 6), 256, 0, s1>>>(
        h, o + sRow, gate_w, gate_b, scale_p, dl + sRow);

    // -------- chamber 0 on stream 0 (needed by both branches) --------------
    mma_gemm<false, false, false, false><<<dim3(6, 32, 1), 256>>>(
        h, DD, 0, wq, DD, 0, 0, q2, DD, 0, BT, DD, DD, 1.f, 0, 0);
    mma_gemm<false, false, false, false><<<dim3(6, 32, 1), 256>>>(
        h, DD, 0, wk, DD, 0, 0, k2, DD, 0, BT, DD, DD, 1.f, 0, 0);
    mma_gemm<true, false, true, false><<<dim3(8, 8, BB), 256>>>(
        q2, DD, sBT, k2, DD, sBT, 0, S2, TT, sS, TT, TT, DD, isd, 0, 0);
    softmax_causal_kernel<<<BB * TT, 256>>>(S2);
    mma_gemm<false, false, false, true><<<dim3(6, 8, BB), 256>>>(
        S2, TT, sS, h, DD, sBT, 0, o2, DD, sBT, TT, DD, TT, 1.f, 0, 0);
    combine_c0_kernel<<<BT, 256>>>(h, o2, gate_w, gate_b, scale_p, dl, seq);

    // delta_0 ready -> merge GEMM on s1 (single K=7*768 GEMM, A chunked)
    cudaEventRecord(evF2, 0);
    cudaStreamWaitEvent(s1, evF2, 0);
    mma_gemm<true, false, false, false><<<dim3(6, 32, 1), 256, 0, s1>>>(
        dl, DD, 0, mw, NCH * DD, 0, 0, par, DD, 0,
        BT, DD, NCH * DD, 1.f, DD, sRow);
    cudaEventRecord(evJ, s1);

    // -------- sequential chambers 1..6 on stream 0 -------------------------
    const int n4 = BT * DD / 4;
    for (int i = 1; i < NCH; i++) {
        add_round_kernel<<<(n4 + 255) / 256, 256>>>(h, seq, inb, n4);
        mma_gemm<false, false, false, false><<<dim3(6, 32, 1), 256>>>(
            inb, DD, 0, wq + (size_t)i * sQK, DD, 0, 0,
            q2, DD, 0, BT, DD, DD, 1.f, 0, 0);
        mma_gemm<false, false, false, false><<<dim3(6, 32, 1), 256>>>(
            inb, DD, 0, wk + (size_t)i * sQK, DD, 0, 0,
            k2, DD, 0, BT, DD, DD, 1.f, 0, 0);
        mma_gemm<true, false, true, false><<<dim3(8, 8, BB), 256>>>(
            q2, DD, sBT, k2, DD, sBT, 0, S2, TT, sS, TT, TT, DD, isd, 0, 0);
        softmax_causal_kernel<<<BB * TT, 256>>>(S2);
        mma_gemm<false, false, false, true><<<dim3(6, 8, BB), 256>>>(
            S2, TT, sS, inb, DD, sBT, 0, o2, DD, sBT, TT, DD, TT, 1.f, 0, 0);
        combine_seq_kernel<<<BT, 256>>>(inb, o2, gate_w + (size_t)i * DD,
                                        gate_b + i, scale_p + i, seq);
    }

    // -------- join + finalize ----------------------------------------------
    cudaStreamWaitEvent(0, evJ, 0);
    final_kernel<<<BT, 256>>>(x, seq, par, ln_post_g, ln_post_b,
                              mode_logit, residual_gate, out);
}

// round 11
// speedup vs baseline: 1.0827x; 1.0827x over previous
#include <cuda_runtime.h>
#include <stdint.h>
#include <math.h>

// Problem constants
#define BB  4
#define TT  1024
#define DD  768
#define NCH 7
#define BT  (BB*TT)   // 4096 rows

// ---------------------------------------------------------------------------
// Scratch (device globals; no allocation allowed in kernel_launch)
// ---------------------------------------------------------------------------
__device__ float g_h   [(size_t)BT*DD];
__device__ float g_in  [(size_t)BT*DD];
__device__ float g_seq [(size_t)BT*DD];
__device__ float g_par [(size_t)BT*DD];
// parallel branch (chambers 1..6 use slots 1..6; slot 0 unused)
__device__ float g_q   [(size_t)NCH*BT*DD];
__device__ float g_k   [(size_t)NCH*BT*DD];
__device__ float g_o   [(size_t)NCH*BT*DD];
__device__ float g_d   [(size_t)NCH*BT*DD];
__device__ float g_S   [(size_t)NCH*BB*TT*TT];
// sequential-branch private buffers
__device__ float g_qk2 [(size_t)2*BT*DD];      // fused Q|K output
__device__ float g_o2  [(size_t)BT*DD];
__device__ float g_S2  [(size_t)BB*TT*TT];
// TF32-rounded weights: interleaved [chamber][q|k][D][D], plus merge
__device__ float g_wqk [(size_t)NCH*2*DD*DD];
__device__ float g_mw  [(size_t)DD*NCH*DD];

// ---------------------------------------------------------------------------
// TF32 helpers
// ---------------------------------------------------------------------------
__device__ __forceinline__ uint32_t f2tf(float f) {
    uint32_t r;
    asm("cvt.rna.tf32.f32 %0, %1;" : "=r"(r) : "f"(f));
    return r;
}
__device__ __forceinline__ float tf32r(float f) { return __uint_as_float(f2tf(f)); }

__device__ __forceinline__ void mma_tf32(float c[4],
    uint32_t a0, uint32_t a1, uint32_t a2, uint32_t a3,
    uint32_t b0, uint32_t b1)
{
    asm volatile(
        "mma.sync.aligned.m16n8k8.row.col.f32.tf32.tf32.f32 "
        "{%0,%1,%2,%3}, {%4,%5,%6,%7}, {%8,%9}, {%0,%1,%2,%3};"
        : "+f"(c[0]), "+f"(c[1]), "+f"(c[2]), "+f"(c[3])
        : "r"(a0), "r"(a1), "r"(a2), "r"(a3), "r"(b0), "r"(b1));
}
#define CPA16(saddr, gptr) \
    asm volatile("cp.async.cg.shared.global [%0], [%1], 16;" :: "r"(saddr), "l"(gptr))
#define CPA_COMMIT() asm volatile("cp.async.commit_group;")
#define CPA_WAIT2()  asm volatile("cp.async.wait_group 2;")

// ---------------------------------------------------------------------------
// TF32 MMA GEMM, 4-stage cp.async pipeline, dynamic smem.
// C = round_tf32( alpha * A @ op(B) (+ C if ACC) )
// Operands must already be TF32-rounded (producers round at write).
//   A: M x K row-major (lda). kchunk>0: K-concat of chunks (merge GEMM).
//   B: TRANSB ? N x K row-major : K x N row-major. bmod>0 -> B uses z%bmod.
//   CSKIP: skip C tiles fully above diagonal. CKLIM: cap K at tile diagonal.
// Tiles 128x128x16, 8 warps, 64x32 warp tile.
// ---------------------------------------------------------------------------
#define ASTRIDE 20
#define BSTRIDE 136
#define AS_SZ  (128*ASTRIDE)
#define STG_SZ (2*AS_SZ)          // 5120 floats = 20 KB per stage
#define NSTG   4
#define GEMM_SMEM (NSTG*STG_SZ*(int)sizeof(float))   // 81920 B

template<bool TRANSB, bool ACC, bool CSKIP, bool CKLIM>
__global__ void __launch_bounds__(256, 2)
mma_gemm(const float* __restrict__ A, int lda, long long sA,
         const float* __restrict__ Bp, int ldb, long long sB, int bmod,
         float* __restrict__ C, int ldc, long long sC,
         int M, int N, int K, float alpha,
         int kchunk, long long schunk)
{
    extern __shared__ float smdyn[];

    const int m0 = blockIdx.y * 128;
    const int n0 = blockIdx.x * 128;
    if (CSKIP && n0 > m0 + 127) return;

    const int z = blockIdx.z;
    A  += (long long)z * sA;
    Bp += (long long)(bmod ? (z % bmod) : z) * sB;
    C  += (long long)z * sC;

    int kend = K;
    if (CKLIM) { int ke = m0 + 128; kend = (ke < K) ? ke : K; }
    const int niter = kend >> 4;   // always >= 8 here

    const int tid  = threadIdx.x;
    const int wid  = tid >> 5;
    const int lane = tid & 31;
    const int gid  = lane >> 2;
    const int tig  = lane & 3;
    const int wm   = (wid & 1) * 64;
    const int wn   = (wid >> 1) * 32;

    float acc[4][4][4];
    #pragma unroll
    for (int i = 0; i < 4; i++)
        #pragma unroll
        for (int j = 0; j < 4; j++)
            #pragma unroll
            for (int r = 0; r < 4; r++) acc[i][j][r] = 0.f;

    auto loadA = [&](int stg, int k0) {
        const float* Ab;
        if (kchunk) { int c = k0 / kchunk; Ab = A + (long long)c * schunk + (k0 - c * kchunk); }
        else        Ab = A + k0;
        float* as = smdyn + stg * STG_SZ;
        #pragma unroll
        for (int i = 0; i < 2; i++) {
            int idx = tid + i * 256;
            int r = idx >> 2, c4 = (idx & 3) << 2;
            uint32_t sa = (uint32_t)__cvta_generic_to_shared(&as[r * ASTRIDE + c4]);
            CPA16(sa, Ab + (long long)(m0 + r) * lda + c4);
        }
    };
    auto loadB = [&](int stg, int k0) {
        float* bs = smdyn + stg * STG_SZ + AS_SZ;
        if (TRANSB) {
            #pragma unroll
            for (int i = 0; i < 2; i++) {
                int idx = tid + i * 256;
                int r = idx >> 2, c4 = (idx & 3) << 2;
                uint32_t sa = (uint32_t)__cvta_generic_to_shared(&bs[r * ASTRIDE + c4]);
                CPA16(sa, Bp + (long long)(n0 + r) * ldb + k0 + c4);
            }
        } else {
            #pragma unroll
            for (int i = 0; i < 2; i++) {
                int idx = tid + i * 256;
                int r = idx >> 5, c4 = (idx & 31) << 2;
                uint32_t sa = (uint32_t)__cvta_generic_to_shared(&bs[r * BSTRIDE + c4]);
                CPA16(sa, Bp + (long long)(k0 + r) * ldb + n0 + c4);
            }
        }
    };

    // prologue: stages 0,1,2 (niter >= 8 always)
    loadA(0, 0);       loadB(0, 0);       CPA_COMMIT();
    loadA(1, 1 << 4);  loadB(1, 1 << 4);  CPA_COMMIT();
    loadA(2, 2 << 4);  loadB(2, 2 << 4);  CPA_COMMIT();

    for (int it = 0; it < niter; ++it) {
        CPA_WAIT2();            // group 'it' complete; it+1, it+2 may be in flight
        __syncthreads();        // all threads done computing stage (it-1)&3
        const int ld = it + 3;  // refill buffer (it-1)&3
        if (ld < niter) { loadA(ld & 3, ld << 4); loadB(ld & 3, ld << 4); }
        CPA_COMMIT();           // commit (possibly empty) to keep group accounting uniform

        const float* as = smdyn + (it & 3) * STG_SZ;
        const float* bs = as + AS_SZ;

        #pragma unroll
        for (int kk = 0; kk < 16; kk += 8) {
            uint32_t a[4][4];
            #pragma unroll
            for (int mi = 0; mi < 4; mi++) {
                int mb = wm + mi * 16 + gid;
                a[mi][0] = __float_as_uint(as[ mb      * ASTRIDE + kk + tig    ]);
                a[mi][1] = __float_as_uint(as[(mb + 8) * ASTRIDE + kk + tig    ]);
                a[mi][2] = __float_as_uint(as[ mb      * ASTRIDE + kk + tig + 4]);
                a[mi][3] = __float_as_uint(as[(mb + 8) * ASTRIDE + kk + tig + 4]);
            }
            uint32_t b[4][2];
            #pragma unroll
            for (int ni = 0; ni < 4; ni++) {
                int nb = wn + ni * 8 + gid;
                if (TRANSB) {
                    b[ni][0] = __float_as_uint(bs[nb * ASTRIDE + kk + tig    ]);
                    b[ni][1] = __float_as_uint(bs[nb * ASTRIDE + kk + tig + 4]);
                } else {
                    b[ni][0] = __float_as_uint(bs[(kk + tig    ) * BSTRIDE + nb]);
                    b[ni][1] = __float_as_uint(bs[(kk + tig + 4) * BSTRIDE + nb]);
                }
            }
            #pragma unroll
            for (int mi = 0; mi < 4; mi++)
                #pragma unroll
                for (int ni = 0; ni < 4; ni++)
                    mma_tf32(acc[mi][ni], a[mi][0], a[mi][1], a[mi][2], a[mi][3],
                             b[ni][0], b[ni][1]);
        }
    }

    // epilogue — TF32-rounded so downstream GEMMs skip cvt
    #pragma unroll
    for (int mi = 0; mi < 4; mi++) {
        #pragma unroll
        for (int ni = 0; ni < 4; ni++) {
            const int rr = m0 + wm + mi * 16 + gid;
            const int cc = n0 + wn + ni * 8 + tig * 2;
            #pragma unroll
            for (int hh = 0; hh < 2; hh++) {
                long long idx = (long long)(rr + hh * 8) * ldc + cc;
                float2 v;
                v.x = alpha * acc[mi][ni][hh * 2 + 0];
                v.y = alpha * acc[mi][ni][hh * 2 + 1];
                if (ACC) {
                    float2 c = *reinterpret_cast<const float2*>(&C[idx]);
                    v.x += c.x; v.y += c.y;
                }
                v.x = tf32r(v.x);
                v.y = tf32r(v.y);
                *reinterpret_cast<float2*>(&C[idx]) = v;
            }
        }
    }
}

// ---------------------------------------------------------------------------
// Weight rounding kernels
// ---------------------------------------------------------------------------
__global__ void round_tf32_kernel(const float* __restrict__ in,
                                  float* __restrict__ out, int n4)
{
    int i = blockIdx.x * 256 + threadIdx.x;
    if (i < n4) {
        float4 v = reinterpret_cast<const float4*>(in)[i];
        v.x = tf32r(v.x); v.y = tf32r(v.y); v.z = tf32r(v.z); v.w = tf32r(v.w);
        reinterpret_cast<float4*>(out)[i] = v;
    }
}

// Round + interleave into wqk[(2*chamber+which)*D*D + rem]
__global__ void round_inter_kernel(const float* __restrict__ in,
                                   float* __restrict__ out, int which, int n4)
{
    const int q4 = DD * DD / 4;
    int i = blockIdx.x * 256 + threadIdx.x;
    if (i < n4) {
        int c = i / q4, rem = i - c * q4;
        float4 v = reinterpret_cast<const float4*>(in)[i];
        v.x = tf32r(v.x); v.y = tf32r(v.y); v.z = tf32r(v.z); v.w = tf32r(v.w);
        reinterpret_cast<float4*>(out)[(2 * c + which) * q4 + rem] = v;
    }
}

// ---------------------------------------------------------------------------
// Causal softmax in place (rows of [nz][T][T]); TF32-rounded, zero-filled
// to the 128 tile boundary.
// ---------------------------------------------------------------------------
__global__ void __launch_bounds__(256)
softmax_causal_kernel(float* __restrict__ S)
{
    __shared__ float red[256];
    const int r = blockIdx.x;
    const int zb = r / TT, t = r % TT;
    float* row = S + (long long)zb * TT * TT + (long long)t * TT;
    const int valid = t + 1;
    const int tid = threadIdx.x;

    float mx = -1e30f;
    for (int s = tid; s < valid; s += 256) mx = fmaxf(mx, row[s]);
    red[tid] = mx; __syncthreads();
    for (int o = 128; o > 0; o >>= 1) {
        if (tid < o) red[tid] = fmaxf(red[tid], red[tid + o]);
        __syncthreads();
    }
    mx = red[0]; __syncthreads();

    float sum = 0.f;
    for (int s = tid; s < valid; s += 256) {
        float e = expf(row[s] - mx);
        row[s] = e;
        sum += e;
    }
    red[tid] = sum; __syncthreads();
    for (int o = 128; o > 0; o >>= 1) {
        if (tid < o) red[tid] += red[tid + o];
        __syncthreads();
    }
    const float inv = 1.f / red[0];

    for (int s = tid; s < valid; s += 256) row[s] = tf32r(row[s] * inv);
    const int zend = ((valid + 127) / 128) * 128;
    for (int s = valid + tid; s < zend; s += 256) row[s] = 0.f;
}

// ---------------------------------------------------------------------------
// Chamber 0 combine (In == h): v = softplus(sp0)*sigmoid(h.gw0+gb0)*(O-h)
// delta = round(v); seq = v; inb = round(h + v)   [feeds sequential iter 1]
// ---------------------------------------------------------------------------
__global__ void __launch_bounds__(256)
combine_c0_kernel(const float* __restrict__ In, const float* __restrict__ O,
                  const float* __restrict__ gw, const float* __restrict__ gb,
                  const float* __restrict__ sp,
                  float* __restrict__ delta, float* __restrict__ seq,
                  float* __restrict__ inb)
{
    __shared__ float red[256];
    const int r = blockIdx.x;
    const long long base = (long long)r * DD;
    const int tid = threadIdx.x;

    float dot = 0.f;
    for (int d = tid; d < DD; d += 256) dot += In[base + d] * gw[d];
    red[tid] = dot; __syncthreads();
    for (int o = 128; o > 0; o >>= 1) {
        if (tid < o) red[tid] += red[tid + o];
        __syncthreads();
    }
    const float gate = 1.f / (1.f + expf(-(red[0] + gb[0])));
    const float s = sp[0];
    float coef = (s > 20.f) ? s : log1pf(expf(s));
    coef *= gate;

    for (int d = tid; d < DD; d += 256) {
        const float hv = In[base + d];
        const float v = coef * (O[base + d] - hv);
        delta[base + d] = tf32r(v);
        seq[base + d] = v;
        inb[base + d] = tf32r(hv + v);
    }
}

// ---------------------------------------------------------------------------
// Parallel combine for chambers 1..6 (blockIdx.y = ch-1)
// ---------------------------------------------------------------------------
__global__ void __launch_bounds__(256)
combine_par6_kernel(const float* __restrict__ hIn, const float* __restrict__ o6,
                    const float* __restrict__ gw, const float* __restrict__ gb,
                    const float* __restrict__ sp, float* __restrict__ delta6)
{
    __shared__ float red[256];
    const int i  = blockIdx.y;
    const int r  = blockIdx.x;
    const long long base  = (long long)r * DD;
    const long long cbase = (long long)i * BT * DD + base;
    const int tid = threadIdx.x;
    const float* gwi = gw + (size_t)(i + 1) * DD;

    float dot = 0.f;
    for (int d = tid; d < DD; d += 256) dot += hIn[base + d] * gwi[d];
    red[tid] = dot; __syncthreads();
    for (int o = 128; o > 0; o >>= 1) {
        if (tid < o) red[tid] += red[tid + o];
        __syncthreads();
    }
    const float gate = 1.f / (1.f + expf(-(red[0] + gb[i + 1])));
    const float s = sp[i + 1];
    float coef = (s > 20.f) ? s : log1pf(expf(s));
    coef *= gate;

    for (int d = tid; d < DD; d += 256)
        delta6[cbase + d] = tf32r(coef * (o6[cbase + d] - hIn[base + d]));
}

// ---------------------------------------------------------------------------
// Sequential combine: seq += v; inb = round(h + seq_new)  (inb may be null)
// ---------------------------------------------------------------------------
__global__ void __launch_bounds__(256)
combine_seq_kernel(const float* __restrict__ In, const float* __restrict__ O,
                   const float* __restrict__ h,
                   const float* __restrict__ gw, const float* __restrict__ gb,
                   const float* __restrict__ sp,
                   float* __restrict__ seq, float* __restrict__ inb)
{
    __shared__ float red[256];
    const int r = blockIdx.x;
    const long long base = (long long)r * DD;
    const int tid = threadIdx.x;

    float dot = 0.f;
    for (int d = tid; d < DD; d += 256) dot += In[base + d] * gw[d];
    red[tid] = dot; __syncthreads();
    for (int o = 128; o > 0; o >>= 1) {
        if (tid < o) red[tid] += red[tid + o];
        __syncthreads();
    }
    const float gate = 1.f / (1.f + expf(-(red[0] + gb[0])));
    const float s = sp[0];
    float coef = (s > 20.f) ? s : log1pf(expf(s));
    coef *= gate;

    for (int d = tid; d < DD; d += 256) {
        const float sv = seq[base + d] + coef * (O[base + d] - In[base + d]);
        seq[base + d] = sv;
        if (inb) inb[base + d] = tf32r(h[base + d] + sv);
    }
}

// ---------------------------------------------------------------------------
// LayerNorm (per row), output TF32-rounded (feeds GEMMs)
// ---------------------------------------------------------------------------
__global__ void __launch_bounds__(256)
ln_kernel(const float* __restrict__ x, const float* __restrict__ g,
          const float* __restrict__ b, float* __restrict__ out)
{
    __shared__ float r1[256], r2[256];
    const int r = blockIdx.x;
    const long long base = (long long)r * DD;
    const int tid = threadIdx.x;

    float s = 0.f, s2 = 0.f;
    for (int d = tid; d < DD; d += 256) {
        float v = x[base + d];
        s += v; s2 += v * v;
    }
    r1[tid] = s; r2[tid] = s2; __syncthreads();
    for (int o = 128; o > 0; o >>= 1) {
        if (tid < o) { r1[tid] += r1[tid + o]; r2[tid] += r2[tid + o]; }
        __syncthreads();
    }
    const float m   = r1[0] / DD;
    const float var = r2[0] / DD - m * m;
    const float inv = rsqrtf(var + 1e-5f);
    for (int d = tid; d < DD; d += 256)
        out[base + d] = tf32r((x[base + d] - m) * inv * g[d] + b[d]);
}

// ---------------------------------------------------------------------------
__global__ void __launch_bounds__(256)
final_kernel(const float* __restrict__ x, const float* __restrict__ seq,
             const float* __restrict__ par, const float* __restrict__ g,
             const float* __restrict__ b, const float* __restrict__ mode_logit,
             const float* __restrict__ res_gate, float* __restrict__ out)
{
    __shared__ float r1[256], r2[256];
    const int r = blockIdx.x;
    const long long base = (long long)r * DD;
    const int tid = threadIdx.x;

    const float mg = 1.f / (1.f + expf(-mode_logit[0]));
    const float rg = res_gate[0];

    float s = 0.f, s2 = 0.f;
    for (int d = tid; d < DD; d += 256) {
        float e = (1.f - mg) * seq[base + d] + mg * par[base + d];
        s += e; s2 += e * e;
    }
    r1[tid] = s; r2[tid] = s2; __syncthreads();
    for (int o = 128; o > 0; o >>= 1) {
        if (tid < o) { r1[tid] += r1[tid + o]; r2[tid] += r2[tid + o]; }
        __syncthreads();
    }
    const float m   = r1[0] / DD;
    const float var = r2[0] / DD - m * m;
    const float inv = rsqrtf(var + 1e-5f);
    for (int d = tid; d < DD; d += 256) {
        float e  = (1.f - mg) * seq[base + d] + mg * par[base + d];
        float ln = (e - m) * inv * g[d] + b[d];
        out[base + d] = x[base + d] + rg * ln;
    }
}

// ---------------------------------------------------------------------------
extern "C" void kernel_launch(void* const* d_in, const int* in_sizes, int n_in,
                              void* d_out, int out_size)
{
    const float* x             = (const float*)d_in[0];
    const float* Wq            = (const float*)d_in[1];
    const float* Wk            = (const float*)d_in[2];
    const float* gate_w        = (const float*)d_in[3];
    const float* gate_b        = (const float*)d_in[4];
    const float* scale_p       = (const float*)d_in[5];
    const float* merge_W       = (const float*)d_in[6];
    const float* mode_logit    = (const float*)d_in[7];
    const float* residual_gate = (const float*)d_in[8];
    const float* ln_pre_g      = (const float*)d_in[9];
    const float* ln_pre_b      = (const float*)d_in[10];
    const float* ln_post_g     = (const float*)d_in[11];
    const float* ln_post_b     = (const float*)d_in[12];
    float* out = (float*)d_out;

    float *h, *inb, *seq, *par, *q, *k, *o, *dl, *S;
    float *qk2, *o2, *S2, *wqk, *mw;
    cudaGetSymbolAddress((void**)&h,   g_h);
    cudaGetSymbolAddress((void**)&inb, g_in);
    cudaGetSymbolAddress((void**)&seq, g_seq);
    cudaGetSymbolAddress((void**)&par, g_par);
    cudaGetSymbolAddress((void**)&q,   g_q);
    cudaGetSymbolAddress((void**)&k,   g_k);
    cudaGetSymbolAddress((void**)&o,   g_o);
    cudaGetSymbolAddress((void**)&dl,  g_d);
    cudaGetSymbolAddress((void**)&S,   g_S);
    cudaGetSymbolAddress((void**)&qk2, g_qk2);
    cudaGetSymbolAddress((void**)&o2,  g_o2);
    cudaGetSymbolAddress((void**)&S2,  g_S2);
    cudaGetSymbolAddress((void**)&wqk, g_wqk);
    cudaGetSymbolAddress((void**)&mw,  g_mw);

    // One-time host resources + dynamic-smem opt-in (first call precedes capture)
    static cudaStream_t s1 = nullptr;
    static cudaEvent_t evF1 = nullptr, evF2 = nullptr, evJ = nullptr;
    if (!s1) {
        cudaStreamCreateWithFlags(&s1, cudaStreamNonBlocking);
        cudaEventCreateWithFlags(&evF1, cudaEventDisableTiming);
        cudaEventCreateWithFlags(&evF2, cudaEventDisableTiming);
        cudaEventCreateWithFlags(&evJ,  cudaEventDisableTiming);
        cudaFuncSetAttribute(mma_gemm<false, false, false, false>,
                             cudaFuncAttributeMaxDynamicSharedMemorySize, GEMM_SMEM);
        cudaFuncSetAttribute(mma_gemm<true,  false, true,  false>,
                             cudaFuncAttributeMaxDynamicSharedMemorySize, GEMM_SMEM);
        cudaFuncSetAttribute(mma_gemm<false, false, false, true >,
                             cudaFuncAttributeMaxDynamicSharedMemorySize, GEMM_SMEM);
        cudaFuncSetAttribute(mma_gemm<true,  false, false, false>,
                             cudaFuncAttributeMaxDynamicSharedMemorySize, GEMM_SMEM);
    }

    const float isd = 1.f / sqrtf((float)DD);
    const long long sQK  = (long long)DD * DD;
    const long long sRow = (long long)BT * DD;
    const long long sBT  = (long long)TT * DD;
    const long long sS   = (long long)TT * TT;
    const int wn4 = NCH * DD * DD / 4;
    float* q2 = qk2;
    float* k2 = qk2 + sRow;

    // -------- weight rounding (interleaved q|k) + pre-LN --------------------
    round_inter_kernel<<<(wn4 + 255) / 256, 256>>>(Wq, wqk, 0, wn4);
    round_inter_kernel<<<(wn4 + 255) / 256, 256>>>(Wk, wqk, 1, wn4);
    ln_kernel<<<BT, 256>>>(x, ln_pre_g, ln_pre_b, h);

    // -------- fork: s1 runs parallel chambers 1..6 + merge weight round ----
    cudaEventRecord(evF1, 0);
    cudaStreamWaitEvent(s1, evF1, 0);

    round_tf32_kernel<<<(wn4 + 255) / 256, 256, 0, s1>>>(merge_W, mw, wn4);
    // Q_i = h @ Wq_i (chambers 1..6): interleaved weights, stride 2*sQK
    mma_gemm<false, false, false, false><<<dim3(6, 32, 6), 256, GEMM_SMEM, s1>>>(
        h, DD, 0, wqk + 2 * sQK, DD, 2 * sQK, 0, q + sRow, DD, sRow, BT, DD, DD, 1.f, 0, 0);
    mma_gemm<false, false, false, false><<<dim3(6, 32, 6), 256, GEMM_SMEM, s1>>>(
        h, DD, 0, wqk + 3 * sQK, DD, 2 * sQK, 0, k + sRow, DD, sRow, BT, DD, DD, 1.f, 0, 0);
    mma_gemm<true, false, true, false><<<dim3(8, 8, 24), 256, GEMM_SMEM, s1>>>(
        q + sRow, DD, sBT, k + sRow, DD, sBT, 0, S, TT, sS, TT, TT, DD, isd, 0, 0);
    softmax_causal_kernel<<<24 * TT, 256, 0, s1>>>(S);
    mma_gemm<false, false, false, true><<<dim3(6, 8, 24), 256, GEMM_SMEM, s1>>>(
        S, TT, sS, h, DD, sBT, BB, o + sRow, DD, sBT, TT, DD, TT, 1.f, 0, 0);
    combine_par6_kernel<<<dim3(BT, 6), 256, 0, s1>>>(
        h, o + sRow, gate_w, gate_b, scale_p, dl + sRow);

    // -------- chamber 0 on stream 0 (fused Q|K launch, z=2) -----------------
    mma_gemm<false, false, false, false><<<dim3(6, 32, 2), 256, GEMM_SMEM>>>(
        h, DD, 0, wqk, DD, sQK, 0, qk2, DD, sRow, BT, DD, DD, 1.f, 0, 0);
    mma_gemm<true, false, true, false><<<dim3(8, 8, BB), 256, GEMM_SMEM>>>(
        q2, DD, sBT, k2, DD, sBT, 0, S2, TT, sS, TT, TT, DD, isd, 0, 0);
    softmax_causal_kernel<<<BB * TT, 256>>>(S2);
    mma_gemm<false, false, false, true><<<dim3(6, 8, BB), 256, GEMM_SMEM>>>(
        S2, TT, sS, h, DD, sBT, 0, o2, DD, sBT, TT, DD, TT, 1.f, 0, 0);
    combine_c0_kernel<<<BT, 256>>>(h, o2, gate_w, gate_b, scale_p, dl, seq, inb);

    // delta_0 ready -> merge GEMM on s1 (single K=7*768 GEMM, A chunked)
    cudaEventRecord(evF2, 0);
    cudaStreamWaitEvent(s1, evF2, 0);
    mma_gemm<true, false, false, false><<<dim3(6, 32, 1), 256, GEMM_SMEM, s1>>>(
        dl, DD, 0, mw, NCH * DD, 0, 0, par, DD, 0,
        BT, DD, NCH * DD, 1.f, DD, sRow);
    cudaEventRecord(evJ, s1);

    // -------- sequential chambers 1..6 on stream 0 -------------------------
    for (int i = 1; i < NCH; i++) {
        // fused Q|K projection from inb (z=2)
        mma_gemm<false, false, false, false><<<dim3(6, 32, 2), 256, GEMM_SMEM>>>(
            inb, DD, 0, wqk + (size_t)i * 2 * sQK, DD, sQK, 0,
            qk2, DD, sRow, BT, DD, DD, 1.f, 0, 0);
        mma_gemm<true, false, true, false><<<dim3(8, 8, BB), 256, GEMM_SMEM>>>(
            q2, DD, sBT, k2, DD, sBT, 0, S2, TT, sS, TT, TT, DD, isd, 0, 0);
        softmax_causal_kernel<<<BB * TT, 256>>>(S2);
        mma_gemm<false, false, false, true><<<dim3(6, 8, BB), 256, GEMM_SMEM>>>(
            S2, TT, sS, inb, DD, sBT, 0, o2, DD, sBT, TT, DD, TT, 1.f, 0, 0);
        combine_seq_kernel<<<BT, 256>>>(inb, o2, h, gate_w + (size_t)i * DD,
                                        gate_b + i, scale_p + i, seq,
                                        (i + 1 < NCH) ? inb : nullptr);
    }

    // -------- join + finalize ----------------------------------------------
    cudaStreamWaitEvent(0, evJ, 0);
    final_kernel<<<BT, 256>>>(x, seq, par, ln_post_g, ln_post_b,
                              mode_logit, residual_gate, out);
}